// round 10
// baseline (speedup 1.0000x reference)
#include <cuda_runtime.h>
#include <cuda_fp16.h>
#include <math.h>
#include <stdint.h>

#define Bc 4
#define Tc 256
#define Uc 128
#define Ec 512
#define Dc 640
#define Hc 512
#define Vc 640

// Scratch (no cudaMalloc allowed).
__device__ float  g_enc[Bc * Tc * Hc];   // [B*T, H]
__device__ float  g_dec[Bc * Uc * Hc];   // [B*U, H]
__device__ __half g_Wt[Vc * Hc];         // W_out^T fp16: [V, H]

// ---------------------------------------------------------------------------
// Helpers (sm_80-era PTX only — no 'a'-gated instructions)
// ---------------------------------------------------------------------------
__device__ __forceinline__ uint32_t smem_u32(const void* p) {
    return (uint32_t)__cvta_generic_to_shared(p);
}
__device__ __forceinline__ void cp16(uint32_t dst, const void* src) {
    asm volatile("cp.async.cg.shared.global [%0], [%1], 16;"
                 :: "r"(dst), "l"(src) : "memory");
}
__device__ __forceinline__ void cp_commit() {
    asm volatile("cp.async.commit_group;" ::: "memory");
}
__device__ __forceinline__ void cp_wait1() {
    asm volatile("cp.async.wait_group 1;" ::: "memory");
}
__device__ __forceinline__ void ldmx4(uint32_t* r, uint32_t addr) {
    asm volatile("ldmatrix.sync.aligned.m8n8.x4.shared.b16 {%0,%1,%2,%3}, [%4];"
                 : "=r"(r[0]), "=r"(r[1]), "=r"(r[2]), "=r"(r[3]) : "r"(addr));
}
__device__ __forceinline__ void mma16816(float* d, const uint32_t* a,
                                         uint32_t b0, uint32_t b1) {
    asm volatile(
        "mma.sync.aligned.m16n8k16.row.col.f32.f16.f16.f32 "
        "{%0,%1,%2,%3}, {%4,%5,%6,%7}, {%8,%9}, {%0,%1,%2,%3};"
        : "+f"(d[0]), "+f"(d[1]), "+f"(d[2]), "+f"(d[3])
        : "r"(a[0]), "r"(a[1]), "r"(a[2]), "r"(a[3]), "r"(b0), "r"(b1));
}
__device__ __forceinline__ float tanh_fast(float x) {
    asm("tanh.approx.f32 %0, %0;" : "+f"(x));
    return x;
}
__device__ __forceinline__ uint32_t pack2(float a, float b) {
    __half2 h = __floats2half2_rn(a, b);
    return *reinterpret_cast<uint32_t*>(&h);
}
// Swizzle for 64-byte rows: permutes 16B bank-groups across 8 consecutive rows.
#define SW64(r, c) ((uint32_t)(c) ^ ((((uint32_t)(r) >> 1) & 3) << 4))

// ---------------------------------------------------------------------------
// Prep kernel: z=0 enc proj, z=1 dec proj, z=2 W transpose+fp16 (tiled).
// ---------------------------------------------------------------------------
__global__ __launch_bounds__(256, 2) void prep_kernel(
    const float* __restrict__ enc_out, const float* __restrict__ dec_out,
    const float* __restrict__ W_enc, const float* __restrict__ b_enc,
    const float* __restrict__ W_dec, const float* __restrict__ W_out)
{
    int z = blockIdx.z;
    int tid = threadIdx.x;

    if (z == 2) {   // coalesced tiled transpose: g_Wt[v][k] = fp16(W_out[k][v])
        __shared__ float t[32][33];
        int bid = blockIdx.y * 8 + blockIdx.x;     // 128 blocks
        int r0 = tid >> 5, cc = tid & 31;
        for (int tile = bid; tile < 320; tile += 128) {   // 16 kt x 20 vt
            int k0 = (tile / 20) * 32, v0 = (tile % 20) * 32;
            #pragma unroll
            for (int i = 0; i < 4; i++) {
                int r = r0 + i * 8;
                t[r][cc] = W_out[(size_t)(k0 + r) * Vc + v0 + cc];
            }
            __syncthreads();
            #pragma unroll
            for (int i = 0; i < 4; i++) {
                int r = r0 + i * 8;
                g_Wt[(size_t)(v0 + r) * Hc + k0 + cc] = __float2half_rn(t[cc][r]);
            }
            __syncthreads();
        }
        return;
    }

    const float* A; const float* W; const float* bias; float* C; int K;
    if (z == 0) {
        A = enc_out; W = W_enc; bias = b_enc; K = Ec;
        float* p; asm("cvta.global.u64 %0, g_enc;" : "=l"(p)); C = p;
    } else {
        if (blockIdx.y >= 8) return;
        A = dec_out; W = W_dec; bias = nullptr; K = Dc;
        float* p; asm("cvta.global.u64 %0, g_dec;" : "=l"(p)); C = p;
    }
    const int N = Hc;

    __shared__ float As[16][64];
    __shared__ float Ws[16][64];
    int row0 = blockIdx.y * 64, col0 = blockIdx.x * 64;
    int tx = tid & 15, ty = tid >> 4;
    float acc[4][4] = {};

    int rA = tid >> 2, kqA = (tid & 3) * 4;
    int kW = tid >> 4, cqW = (tid & 15) * 4;

    float4 areg = *(const float4*)&A[(size_t)(row0 + rA) * K + kqA];
    float4 wreg = *(const float4*)&W[(size_t)kW * N + col0 + cqW];

    const int NK = K / 16;
    for (int kt = 0; kt < NK; kt++) {
        __syncthreads();
        As[kqA + 0][rA] = areg.x;
        As[kqA + 1][rA] = areg.y;
        As[kqA + 2][rA] = areg.z;
        As[kqA + 3][rA] = areg.w;
        *(float4*)&Ws[kW][cqW] = wreg;
        __syncthreads();
        if (kt + 1 < NK) {
            int k0 = (kt + 1) * 16;
            areg = *(const float4*)&A[(size_t)(row0 + rA) * K + k0 + kqA];
            wreg = *(const float4*)&W[(size_t)(k0 + kW) * N + col0 + cqW];
        }
        #pragma unroll
        for (int kk = 0; kk < 16; kk++) {
            float a[4], b[4];
            #pragma unroll
            for (int i = 0; i < 4; i++) a[i] = As[kk][ty * 4 + i];
            #pragma unroll
            for (int j = 0; j < 4; j++) b[j] = Ws[kk][tx * 4 + j];
            #pragma unroll
            for (int i = 0; i < 4; i++)
                #pragma unroll
                for (int j = 0; j < 4; j++)
                    acc[i][j] += a[i] * b[j];
        }
    }
    #pragma unroll
    for (int i = 0; i < 4; i++) {
        int r = row0 + ty * 4 + i;
        #pragma unroll
        for (int j = 0; j < 4; j++) {
            int c = col0 + tx * 4 + j;
            float v = acc[i][j];
            if (bias) v += bias[c];
            C[(size_t)r * N + c] = v;
        }
    }
}

// ---------------------------------------------------------------------------
// Fused joint kernel v4: CTA = (bt, u-half). 2048 CTAs, 2 CTAs/SM.
//   A[64u x 512k] fp16(tanh.approx(enc+dec)) resident (64KB; 16 chunks of
//   [64x32], 64B rows, SW64 swizzle), filled JIT during v-tile 0.
//   v-tiles: 256, 256, 128. W chunk [Nt x 32k] <=16KB via 3-buf cp.async ring.
//   8 warps. Wide vtiles: warp tile 32x64 (2m x 4n). Narrow vt2: 32x32.
//   ldsm/mma = 0.375 (wide) vs 0.5 at 32x32 — 25% less smem traffic.
// ---------------------------------------------------------------------------
#define KCH 32                      // k per chunk
#define ACH 4096                    // A chunk: 64 rows x 32 halfs
#define NKC 16                      // k-chunks per v-tile
#define WCH 16384                   // W ring buffer stride (256 rows x 32 halfs)
#define W_OFF (16 * ACH)            // A = 64KB
#define JSMEM (W_OFF + 3 * WCH)     // 114688 B = 112KB
#define NIT 48

struct JCtx {
    uint32_t sb;
    const float* encR;
    const float* decB;   // dec rows for this u-half
};

// Fill A chunk kc (64 rows x 32 halfs) — 256 units of 16B, 1 per thread.
__device__ __forceinline__ void fillA(const JCtx& c, int kc, int tid) {
    int r = tid >> 2, cg = tid & 3;
    int kcol = kc * KCH + cg * 8;
    float4 d0 = *(const float4*)(c.decB + (size_t)r * Hc + kcol);
    float4 d1 = *(const float4*)(c.decB + (size_t)r * Hc + kcol + 4);
    float4 e0 = *(const float4*)(c.encR + kcol);
    float4 e1 = *(const float4*)(c.encR + kcol + 4);
    uint4 q;
    q.x = pack2(tanh_fast(d0.x + e0.x), tanh_fast(d0.y + e0.y));
    q.y = pack2(tanh_fast(d0.z + e0.z), tanh_fast(d0.w + e0.w));
    q.z = pack2(tanh_fast(d1.x + e1.x), tanh_fast(d1.y + e1.y));
    q.w = pack2(tanh_fast(d1.z + e1.z), tanh_fast(d1.w + e1.w));
    uint32_t off = (uint32_t)kc * ACH + r * 64 + SW64(r, cg * 16);
    asm volatile("st.shared.v4.b32 [%0], {%1,%2,%3,%4};"
                 :: "r"(c.sb + off), "r"(q.x), "r"(q.y), "r"(q.z), "r"(q.w)
                 : "memory");
}

// Load W chunk i (vt = i/16, kc = i%16): Nt rows x 32 halfs.
__device__ __forceinline__ void loadW(uint32_t sb, int i, int tid) {
    int vt = i >> 4, kc = i & 15;
    int nu = ((vt == 2) ? 128 : 256) * 4;          // 16B units
    uint32_t dstb = sb + W_OFF + (uint32_t)(i % 3) * WCH;
    const __half* src = g_Wt + ((size_t)vt * 256) * Hc + kc * KCH;
    for (int idx = tid; idx < nu; idx += 256) {
        int r = idx >> 2, cg = idx & 3;
        cp16(dstb + r * 64 + SW64(r, cg * 16),
             src + (size_t)r * Hc + cg * 8);
    }
}

// One 32-K chunk of MMAs. NF = number of 8-wide N frags (8 wide, 4 narrow).
template<int NF>
__device__ __forceinline__ void mma_chunk(
    uint32_t Ab, uint32_t Wb, int m0, int n0,
    int rowA, int khA, int rowB, int khB, float acc[2][8][4])
{
    #pragma unroll
    for (int ks = 0; ks < 2; ks++) {
        uint32_t a[2][4], bq[NF / 2][4];
        #pragma unroll
        for (int mf = 0; mf < 2; mf++) {
            int r = m0 + mf * 16 + rowA;
            ldmx4(a[mf], Ab + r * 64 + SW64(r, ks * 32 + khA));
        }
        #pragma unroll
        for (int nb = 0; nb < NF / 2; nb++) {
            int r = n0 + nb * 16 + rowB;
            ldmx4(bq[nb], Wb + r * 64 + SW64(r, ks * 32 + khB));
        }
        #pragma unroll
        for (int mf = 0; mf < 2; mf++)
            #pragma unroll
            for (int nf = 0; nf < NF; nf++)
                mma16816(acc[mf][nf], a[mf],
                         bq[nf >> 1][2 * (nf & 1)], bq[nf >> 1][2 * (nf & 1) + 1]);
    }
}

__global__ __launch_bounds__(256, 2) void joint_kernel(
    const float* __restrict__ bout, float* __restrict__ out)
{
    extern __shared__ char smem[];
    JCtx c;
    c.sb = smem_u32(smem);
    int tid = threadIdx.x, l = tid & 31, w = tid >> 5;
    int bx = blockIdx.x;
    int bt = bx >> 1, uh = bx & 1;
    int b = bt >> 8;
    c.encR = g_enc + (size_t)bt * Hc;
    c.decB = g_dec + ((size_t)b * Uc + uh * 64) * Hc;

    int m0 = (w >> 2) * 32;           // 0 / 32
    int n0w = (w & 3) * 64;           // wide:   0 / 64 / 128 / 192
    int n0n = (w & 3) * 32;           // narrow: 0 / 32 / 64 / 96
    int rowA = l & 15, khA = (l >> 4) * 16;
    int rowB = (l & 7) + ((l >> 4) << 3), khB = ((l >> 3) & 1) * 16;
    int gr = l >> 2, ct = l & 3;

    // Prologue: W chunks 0,1 in flight; A chunk 0 computed.
    loadW(c.sb, 0, tid); cp_commit();
    loadW(c.sb, 1, tid); cp_commit();
    fillA(c, 0, tid);

    float acc[2][8][4];
    float* outbt = out + ((size_t)bt * Uc + uh * 64) * Vc;

    for (int i = 0; i < NIT; i++) {
        int vt = i >> 4, kc = i & 15;
        bool wide = (vt < 2);
        int n0 = wide ? n0w : n0n;
        int NFc = wide ? 8 : 4;
        cp_wait1();
        __syncthreads();   // W chunk i visible; A chunk kc visible (vt==0)

        if (kc == 0) {   // init accumulators from bias
            #pragma unroll
            for (int nf = 0; nf < 8; nf++) {
                if (nf < NFc) {
                    int cc = vt * 256 + n0 + nf * 8 + 2 * ct;
                    float b0 = __ldg(&bout[cc]), b1 = __ldg(&bout[cc + 1]);
                    #pragma unroll
                    for (int mf = 0; mf < 2; mf++) {
                        acc[mf][nf][0] = b0; acc[mf][nf][1] = b1;
                        acc[mf][nf][2] = b0; acc[mf][nf][3] = b1;
                    }
                }
            }
        }

        uint32_t Ab = c.sb + (uint32_t)kc * ACH;
        uint32_t Wb = c.sb + W_OFF + (uint32_t)(i % 3) * WCH;
        if (wide)
            mma_chunk<8>(Ab, Wb, m0, n0, rowA, khA, rowB, khB, acc);
        else
            mma_chunk<4>(Ab, Wb, m0, n0, rowA, khA, rowB, khB, acc);

        if (vt == 0 && kc < 15) fillA(c, kc + 1, tid);   // hidden under MMA
        if (i + 2 < NIT) loadW(c.sb, i + 2, tid);
        cp_commit();   // uniform commit keeps wait_group bookkeeping simple

        if (kc == 15) {   // epilogue for v-tile (bias already in acc)
            #pragma unroll
            for (int nf = 0; nf < 8; nf++) {
                if (nf < NFc) {
                    int cc = vt * 256 + n0 + nf * 8 + 2 * ct;
                    #pragma unroll
                    for (int mf = 0; mf < 2; mf++) {
                        int u = m0 + mf * 16 + gr;
                        float* p = outbt + (size_t)u * Vc + cc;
                        float2 t0; t0.x = acc[mf][nf][0]; t0.y = acc[mf][nf][1];
                        float2 t1; t1.x = acc[mf][nf][2]; t1.y = acc[mf][nf][3];
                        *(float2*)p = t0;
                        *(float2*)(p + 8 * Vc) = t1;
                    }
                }
            }
        }
    }
}

// ---------------------------------------------------------------------------
extern "C" void kernel_launch(void* const* d_in, const int* in_sizes, int n_in,
                              void* d_out, int out_size)
{
    const float* enc_out = (const float*)d_in[0];
    const float* dec_out = (const float*)d_in[1];
    const float* W_enc   = (const float*)d_in[2];
    const float* b_enc   = (const float*)d_in[3];
    const float* W_dec   = (const float*)d_in[4];
    const float* W_out   = (const float*)d_in[5];
    const float* b_out   = (const float*)d_in[6];
    float* out = (float*)d_out;

    cudaFuncSetAttribute(joint_kernel,
                         cudaFuncAttributeMaxDynamicSharedMemorySize, JSMEM);

    prep_kernel<<<dim3(8, 16, 3), 256>>>(enc_out, dec_out, W_enc, b_enc, W_dec, W_out);
    joint_kernel<<<2 * Bc * Tc, 256, JSMEM>>>(b_out, out);
}

// round 11
// speedup vs baseline: 1.3958x; 1.3958x over previous
#include <cuda_runtime.h>
#include <cuda_fp16.h>
#include <math.h>
#include <stdint.h>

#define Bc 4
#define Tc 256
#define Uc 128
#define Ec 512
#define Dc 640
#define Hc 512
#define Vc 640

// Scratch (no cudaMalloc allowed).
__device__ float g_enc[Bc * Tc * Hc];    // [B*T, H]
__device__ float g_dec[Bc * Uc * Hc];    // [B*U, H]
// W_out pre-packed into mma.sync B-fragment layout:
// g_Wf[(nt*32 + kt)*32 + lane] = {pack(W[kt*16+2*(l%4)][nt*8+l/4], W[..+1][..]),
//                                 pack(W[kt*16+2*(l%4)+8][..],    W[..+9][..])}
__device__ uint2 g_Wf[80 * 32 * 32];     // 640KB

// ---------------------------------------------------------------------------
// Helpers (sm_80-era PTX only — no 'a'-gated instructions)
// ---------------------------------------------------------------------------
__device__ __forceinline__ uint32_t smem_u32(const void* p) {
    return (uint32_t)__cvta_generic_to_shared(p);
}
__device__ __forceinline__ void ldmx4(uint32_t* r, uint32_t addr) {
    asm volatile("ldmatrix.sync.aligned.m8n8.x4.shared.b16 {%0,%1,%2,%3}, [%4];"
                 : "=r"(r[0]), "=r"(r[1]), "=r"(r[2]), "=r"(r[3]) : "r"(addr));
}
__device__ __forceinline__ void mma16816(float* d, const uint32_t* a,
                                         uint32_t b0, uint32_t b1) {
    asm volatile(
        "mma.sync.aligned.m16n8k16.row.col.f32.f16.f16.f32 "
        "{%0,%1,%2,%3}, {%4,%5,%6,%7}, {%8,%9}, {%0,%1,%2,%3};"
        : "+f"(d[0]), "+f"(d[1]), "+f"(d[2]), "+f"(d[3])
        : "r"(a[0]), "r"(a[1]), "r"(a[2]), "r"(a[3]), "r"(b0), "r"(b1));
}
__device__ __forceinline__ float tanh_fast(float x) {
    asm("tanh.approx.f32 %0, %0;" : "+f"(x));
    return x;
}
__device__ __forceinline__ uint32_t pack2(float a, float b) {
    __half2 h = __floats2half2_rn(a, b);
    return *reinterpret_cast<uint32_t*>(&h);
}
__device__ __forceinline__ uint32_t pack2h(__half a, __half b) {
    __half2 h = __halves2half2(a, b);
    return *reinterpret_cast<uint32_t*>(&h);
}

// ---------------------------------------------------------------------------
// Prep kernel: z=0 enc proj, z=1 dec proj, z=2 W-fragment builder.
// ---------------------------------------------------------------------------
__global__ __launch_bounds__(256, 2) void prep_kernel(
    const float* __restrict__ enc_out, const float* __restrict__ dec_out,
    const float* __restrict__ W_enc, const float* __restrict__ b_enc,
    const float* __restrict__ W_dec, const float* __restrict__ W_out)
{
    int z = blockIdx.z;
    int tid = threadIdx.x;

    __shared__ float As[16][64];
    __shared__ float Ws[16][64];
    __shared__ __half hbuf[512][8];

    if (z == 2) {   // build g_Wf for ntile nt (8 v-columns, full K)
        int nt = blockIdx.y * 8 + blockIdx.x;
        if (nt >= 80) return;
        #pragma unroll
        for (int i = 0; i < 4; i++) {
            int row = i * 128 + (tid >> 1);
            int c4 = (tid & 1) * 4;
            float4 v = *(const float4*)&W_out[(size_t)row * Vc + nt * 8 + c4];
            hbuf[row][c4 + 0] = __float2half_rn(v.x);
            hbuf[row][c4 + 1] = __float2half_rn(v.y);
            hbuf[row][c4 + 2] = __float2half_rn(v.z);
            hbuf[row][c4 + 3] = __float2half_rn(v.w);
        }
        __syncthreads();
        #pragma unroll
        for (int j = 0; j < 4; j++) {
            int idx = j * 256 + tid;
            int kt = idx >> 5, l = idx & 31;
            int n = l >> 2, k0 = kt * 16 + (l & 3) * 2;
            uint2 q;
            q.x = pack2h(hbuf[k0][n], hbuf[k0 + 1][n]);
            q.y = pack2h(hbuf[k0 + 8][n], hbuf[k0 + 9][n]);
            g_Wf[(nt * 32 + kt) * 32 + l] = q;
        }
        return;
    }

    const float* A; const float* W; const float* bias; float* C; int K;
    if (z == 0) {
        A = enc_out; W = W_enc; bias = b_enc; K = Ec;
        float* p; asm("cvta.global.u64 %0, g_enc;" : "=l"(p)); C = p;
    } else {
        if (blockIdx.y >= 8) return;
        A = dec_out; W = W_dec; bias = nullptr; K = Dc;
        float* p; asm("cvta.global.u64 %0, g_dec;" : "=l"(p)); C = p;
    }
    const int N = Hc;

    int row0 = blockIdx.y * 64, col0 = blockIdx.x * 64;
    int tx = tid & 15, ty = tid >> 4;
    float acc[4][4] = {};

    int rA = tid >> 2, kqA = (tid & 3) * 4;
    int kW = tid >> 4, cqW = (tid & 15) * 4;

    float4 areg = *(const float4*)&A[(size_t)(row0 + rA) * K + kqA];
    float4 wreg = *(const float4*)&W[(size_t)kW * N + col0 + cqW];

    const int NK = K / 16;
    for (int kt = 0; kt < NK; kt++) {
        __syncthreads();
        As[kqA + 0][rA] = areg.x;
        As[kqA + 1][rA] = areg.y;
        As[kqA + 2][rA] = areg.z;
        As[kqA + 3][rA] = areg.w;
        *(float4*)&Ws[kW][cqW] = wreg;
        __syncthreads();
        if (kt + 1 < NK) {
            int k0 = (kt + 1) * 16;
            areg = *(const float4*)&A[(size_t)(row0 + rA) * K + k0 + kqA];
            wreg = *(const float4*)&W[(size_t)(k0 + kW) * N + col0 + cqW];
        }
        #pragma unroll
        for (int kk = 0; kk < 16; kk++) {
            float a[4], b[4];
            #pragma unroll
            for (int i = 0; i < 4; i++) a[i] = As[kk][ty * 4 + i];
            #pragma unroll
            for (int j = 0; j < 4; j++) b[j] = Ws[kk][tx * 4 + j];
            #pragma unroll
            for (int i = 0; i < 4; i++)
                #pragma unroll
                for (int j = 0; j < 4; j++)
                    acc[i][j] += a[i] * b[j];
        }
    }
    #pragma unroll
    for (int i = 0; i < 4; i++) {
        int r = row0 + ty * 4 + i;
        #pragma unroll
        for (int j = 0; j < 4; j++) {
            int c = col0 + tx * 4 + j;
            float v = acc[i][j];
            if (bias) v += bias[c];
            C[(size_t)r * N + c] = v;
        }
    }
}

// ---------------------------------------------------------------------------
// Fused joint kernel v5: CTA = (bt, u-half), 2048 CTAs, 2 CTAs/SM.
//   A[64u x 512k] fp16(tanh.approx(enc+dec)) resident in SMEM (64KB),
//   filled fully up-front; ONE __syncthreads, then zero barriers.
//   B fragments LDG'd directly from g_Wf (pre-packed mma layout) — no W smem,
//   no cp.async, no B-ldmatrix. 1-ks-ahead register prefetch.
//   8 warps, warp tile 64x32 (1m x 8n over CTA 64x256). vt2: 64x16.
// ---------------------------------------------------------------------------
#define JSMEM 65536                 // A only

template<int NF>
__device__ __forceinline__ void run_vt(
    uint32_t sbA, const uint2* __restrict__ wbase,
    const float* __restrict__ bout, float* __restrict__ outbt,
    int vtn0,                       // global v offset of this warp's strip
    int rowA, uint32_t swz, int khA, int l)
{
    int gr = l >> 2, ct = l & 3;
    float acc[4][NF][4];
    #pragma unroll
    for (int nf = 0; nf < NF; nf++) {
        int cc = vtn0 + nf * 8 + 2 * ct;
        float b0 = __ldg(&bout[cc]), b1 = __ldg(&bout[cc + 1]);
        #pragma unroll
        for (int mf = 0; mf < 4; mf++) {
            acc[mf][nf][0] = b0; acc[mf][nf][1] = b1;
            acc[mf][nf][2] = b0; acc[mf][nf][3] = b1;
        }
    }

    uint2 bf[2][NF];
    #pragma unroll
    for (int nb = 0; nb < NF; nb++)
        bf[0][nb] = __ldg(wbase + nb * 1024);

    #pragma unroll 2
    for (int ks = 0; ks < 32; ks++) {
        int cur = ks & 1;
        if (ks < 31) {
            #pragma unroll
            for (int nb = 0; nb < NF; nb++)
                bf[cur ^ 1][nb] = __ldg(wbase + nb * 1024 + (ks + 1) * 32);
        }
        uint32_t bc = (uint32_t)(ks * 32 + khA) ^ swz;
        uint32_t a[4][4];
        #pragma unroll
        for (int mf = 0; mf < 4; mf++)
            ldmx4(a[mf], sbA + (uint32_t)(mf * 16 + rowA) * 1024 + bc);
        #pragma unroll
        for (int mf = 0; mf < 4; mf++)
            #pragma unroll
            for (int nf = 0; nf < NF; nf++)
                mma16816(acc[mf][nf], a[mf], bf[cur][nf].x, bf[cur][nf].y);
    }

    // Epilogue (bias already folded in).
    #pragma unroll
    for (int nf = 0; nf < NF; nf++) {
        int cc = vtn0 + nf * 8 + 2 * ct;
        #pragma unroll
        for (int mf = 0; mf < 4; mf++) {
            int u = mf * 16 + gr;
            float* p = outbt + (size_t)u * Vc + cc;
            float2 t0; t0.x = acc[mf][nf][0]; t0.y = acc[mf][nf][1];
            float2 t1; t1.x = acc[mf][nf][2]; t1.y = acc[mf][nf][3];
            *(float2*)p = t0;
            *(float2*)(p + 8 * Vc) = t1;
        }
    }
}

__global__ __launch_bounds__(256, 2) void joint_kernel(
    const float* __restrict__ bout, float* __restrict__ out)
{
    extern __shared__ char smem[];
    uint32_t sbA = smem_u32(smem);
    int tid = threadIdx.x, l = tid & 31, w = tid >> 5;
    int bx = blockIdx.x;
    int bt = bx >> 1, uh = bx & 1;
    int b = bt >> 8;
    const float* encR = g_enc + (size_t)bt * Hc;
    const float* decB = g_dec + ((size_t)b * Uc + uh * 64) * Hc;

    // Fill A[64][512] fully: rows r have 1024B stride, SW128-style XOR swizzle.
    #pragma unroll
    for (int i = 0; i < 16; i++) {
        int idx = i * 256 + tid;          // 4096 units of 8 halfs
        int r = idx >> 6, cg = idx & 63;
        int kc = cg * 8;
        float4 d0 = *(const float4*)(decB + (size_t)r * Hc + kc);
        float4 d1 = *(const float4*)(decB + (size_t)r * Hc + kc + 4);
        float4 e0 = *(const float4*)(encR + kc);
        float4 e1 = *(const float4*)(encR + kc + 4);
        uint4 q;
        q.x = pack2(tanh_fast(d0.x + e0.x), tanh_fast(d0.y + e0.y));
        q.y = pack2(tanh_fast(d0.z + e0.z), tanh_fast(d0.w + e0.w));
        q.z = pack2(tanh_fast(d1.x + e1.x), tanh_fast(d1.y + e1.y));
        q.w = pack2(tanh_fast(d1.z + e1.z), tanh_fast(d1.w + e1.w));
        uint32_t off = (uint32_t)r * 1024 + (((uint32_t)cg * 16) ^ (((uint32_t)r & 7) << 4));
        asm volatile("st.shared.v4.b32 [%0], {%1,%2,%3,%4};"
                     :: "r"(sbA + off), "r"(q.x), "r"(q.y), "r"(q.z), "r"(q.w)
                     : "memory");
    }
    __syncthreads();   // the ONLY barrier

    int rowA = l & 15, khA = (l >> 4) * 16;
    uint32_t swz = ((uint32_t)l & 7) << 4;
    float* outbt = out + ((size_t)bt * Uc + uh * 64) * Vc;

    // vt0: v in [w*32, w*32+32); vt1: +256; vt2 (128 wide): v in [512 + w*16, +16)
    {
        int n0 = w * 32;
        const uint2* wb = g_Wf + (size_t)(n0 >> 3) * 1024 + l;
        run_vt<4>(sbA, wb, bout, outbt, n0, rowA, swz, khA, l);
    }
    {
        int n0 = 256 + w * 32;
        const uint2* wb = g_Wf + (size_t)(n0 >> 3) * 1024 + l;
        run_vt<4>(sbA, wb, bout, outbt, n0, rowA, swz, khA, l);
    }
    {
        int n0 = 512 + w * 16;
        const uint2* wb = g_Wf + (size_t)(n0 >> 3) * 1024 + l;
        run_vt<2>(sbA, wb, bout, outbt, n0, rowA, swz, khA, l);
    }
}

// ---------------------------------------------------------------------------
extern "C" void kernel_launch(void* const* d_in, const int* in_sizes, int n_in,
                              void* d_out, int out_size)
{
    const float* enc_out = (const float*)d_in[0];
    const float* dec_out = (const float*)d_in[1];
    const float* W_enc   = (const float*)d_in[2];
    const float* b_enc   = (const float*)d_in[3];
    const float* W_dec   = (const float*)d_in[4];
    const float* W_out   = (const float*)d_in[5];
    const float* b_out   = (const float*)d_in[6];
    float* out = (float*)d_out;

    cudaFuncSetAttribute(joint_kernel,
                         cudaFuncAttributeMaxDynamicSharedMemorySize, JSMEM);

    prep_kernel<<<dim3(8, 16, 3), 256>>>(enc_out, dec_out, W_enc, b_enc, W_dec, W_out);
    joint_kernel<<<2 * Bc * Tc, 256, JSMEM>>>(b_out, out);
}

// round 13
// speedup vs baseline: 1.4365x; 1.0291x over previous
#include <cuda_runtime.h>
#include <cuda_fp16.h>
#include <math.h>
#include <stdint.h>

#define Bc 4
#define Tc 256
#define Uc 128
#define Ec 512
#define Dc 640
#define Hc 512
#define Vc 640

// Scratch (no cudaMalloc allowed).
__device__ float g_enc[Bc * Tc * Hc];    // [B*T, H]
__device__ float g_dec[Bc * Uc * Hc];    // [B*U, H]
// W_out pre-packed into mma.sync B-fragment layout:
// g_Wf[(nt*32 + kt)*32 + lane] = {pack(W[kt*16+2*(l%4)][nt*8+l/4], W[..+1][..]),
//                                 pack(W[kt*16+2*(l%4)+8][..],    W[..+9][..])}
__device__ uint2 g_Wf[80 * 32 * 32];     // 640KB

// ---------------------------------------------------------------------------
// Helpers (sm_80-era PTX only — no 'a'-gated instructions)
// ---------------------------------------------------------------------------
__device__ __forceinline__ uint32_t smem_u32(const void* p) {
    return (uint32_t)__cvta_generic_to_shared(p);
}
__device__ __forceinline__ void ldmx4(uint32_t* r, uint32_t addr) {
    asm volatile("ldmatrix.sync.aligned.m8n8.x4.shared.b16 {%0,%1,%2,%3}, [%4];"
                 : "=r"(r[0]), "=r"(r[1]), "=r"(r[2]), "=r"(r[3]) : "r"(addr));
}
__device__ __forceinline__ void mma16816(float* d, const uint32_t* a,
                                         uint32_t b0, uint32_t b1) {
    asm volatile(
        "mma.sync.aligned.m16n8k16.row.col.f32.f16.f16.f32 "
        "{%0,%1,%2,%3}, {%4,%5,%6,%7}, {%8,%9}, {%0,%1,%2,%3};"
        : "+f"(d[0]), "+f"(d[1]), "+f"(d[2]), "+f"(d[3])
        : "r"(a[0]), "r"(a[1]), "r"(a[2]), "r"(a[3]), "r"(b0), "r"(b1));
}
__device__ __forceinline__ float tanh_fast(float x) {
    asm("tanh.approx.f32 %0, %0;" : "+f"(x));
    return x;
}
__device__ __forceinline__ uint32_t pack2(float a, float b) {
    __half2 h = __floats2half2_rn(a, b);
    return *reinterpret_cast<uint32_t*>(&h);
}
__device__ __forceinline__ uint32_t pack2h(__half a, __half b) {
    __half2 h = __halves2half2(a, b);
    return *reinterpret_cast<uint32_t*>(&h);
}

// ---------------------------------------------------------------------------
// Prep kernel: z=0 enc proj, z=1 dec proj, z=2 W-fragment builder.
// Proj: 64x64 tile, BK=32 (half the barrier rounds of BK=16).
// ---------------------------------------------------------------------------
__global__ __launch_bounds__(256, 2) void prep_kernel(
    const float* __restrict__ enc_out, const float* __restrict__ dec_out,
    const float* __restrict__ W_enc, const float* __restrict__ b_enc,
    const float* __restrict__ W_dec, const float* __restrict__ W_out)
{
    int z = blockIdx.z;
    int tid = threadIdx.x;

    __shared__ float As[32][64];
    __shared__ float Ws[32][64];

    if (z == 2) {   // build g_Wf for ntile nt (8 v-columns, full K)
        __shared__ __half hbuf[512][8];
        int nt = blockIdx.y * 8 + blockIdx.x;
        if (nt >= 80) return;
        #pragma unroll
        for (int i = 0; i < 4; i++) {
            int row = i * 128 + (tid >> 1);
            int c4 = (tid & 1) * 4;
            float4 v = *(const float4*)&W_out[(size_t)row * Vc + nt * 8 + c4];
            hbuf[row][c4 + 0] = __float2half_rn(v.x);
            hbuf[row][c4 + 1] = __float2half_rn(v.y);
            hbuf[row][c4 + 2] = __float2half_rn(v.z);
            hbuf[row][c4 + 3] = __float2half_rn(v.w);
        }
        __syncthreads();
        #pragma unroll
        for (int j = 0; j < 4; j++) {
            int idx = j * 256 + tid;
            int kt = idx >> 5, l = idx & 31;
            int n = l >> 2, k0 = kt * 16 + (l & 3) * 2;
            uint2 q;
            q.x = pack2h(hbuf[k0][n], hbuf[k0 + 1][n]);
            q.y = pack2h(hbuf[k0 + 8][n], hbuf[k0 + 9][n]);
            g_Wf[(nt * 32 + kt) * 32 + l] = q;
        }
        return;
    }

    const float* A; const float* W; const float* bias; float* C; int K;
    if (z == 0) {
        A = enc_out; W = W_enc; bias = b_enc; K = Ec;
        float* p; asm("cvta.global.u64 %0, g_enc;" : "=l"(p)); C = p;
    } else {
        if (blockIdx.y >= 8) return;
        A = dec_out; W = W_dec; bias = nullptr; K = Dc;
        float* p; asm("cvta.global.u64 %0, g_dec;" : "=l"(p)); C = p;
    }
    const int N = Hc;

    int row0 = blockIdx.y * 64, col0 = blockIdx.x * 64;
    int tx = tid & 15, ty = tid >> 4;
    float acc[4][4] = {};

    int rA = tid >> 2, kqA = (tid & 3) * 4;    // A rows 0..63, k 0..12
    int kW = tid >> 4, cqW = (tid & 15) * 4;   // W k 0..15, cols

    float4 a0 = *(const float4*)&A[(size_t)(row0 + rA) * K + kqA];
    float4 a1 = *(const float4*)&A[(size_t)(row0 + rA) * K + kqA + 16];
    float4 w0 = *(const float4*)&W[(size_t)kW * N + col0 + cqW];
    float4 w1 = *(const float4*)&W[(size_t)(kW + 16) * N + col0 + cqW];

    const int NK = K / 32;
    for (int kt = 0; kt < NK; kt++) {
        __syncthreads();
        As[kqA + 0][rA] = a0.x; As[kqA + 1][rA] = a0.y;
        As[kqA + 2][rA] = a0.z; As[kqA + 3][rA] = a0.w;
        As[kqA + 16][rA] = a1.x; As[kqA + 17][rA] = a1.y;
        As[kqA + 18][rA] = a1.z; As[kqA + 19][rA] = a1.w;
        *(float4*)&Ws[kW][cqW] = w0;
        *(float4*)&Ws[kW + 16][cqW] = w1;
        __syncthreads();
        if (kt + 1 < NK) {
            int k0 = (kt + 1) * 32;
            a0 = *(const float4*)&A[(size_t)(row0 + rA) * K + k0 + kqA];
            a1 = *(const float4*)&A[(size_t)(row0 + rA) * K + k0 + kqA + 16];
            w0 = *(const float4*)&W[(size_t)(k0 + kW) * N + col0 + cqW];
            w1 = *(const float4*)&W[(size_t)(k0 + kW + 16) * N + col0 + cqW];
        }
        #pragma unroll
        for (int kk = 0; kk < 32; kk++) {
            float a[4], b[4];
            #pragma unroll
            for (int i = 0; i < 4; i++) a[i] = As[kk][ty * 4 + i];
            #pragma unroll
            for (int j = 0; j < 4; j++) b[j] = Ws[kk][tx * 4 + j];
            #pragma unroll
            for (int i = 0; i < 4; i++)
                #pragma unroll
                for (int j = 0; j < 4; j++)
                    acc[i][j] += a[i] * b[j];
        }
    }
    #pragma unroll
    for (int i = 0; i < 4; i++) {
        int r = row0 + ty * 4 + i;
        #pragma unroll
        for (int j = 0; j < 4; j++) {
            int c = col0 + tx * 4 + j;
            float v = acc[i][j];
            if (bias) v += bias[c];
            C[(size_t)r * N + c] = v;
        }
    }
}

// ---------------------------------------------------------------------------
// Fused joint kernel v6: CTA = (bt, u-half), 2048 CTAs, 2 CTAs/SM.
//   A[64u x 512k] fp16(tanh.approx(enc+dec)) resident in SMEM (64KB),
//   filled up-front; ONE __syncthreads, then zero barriers.
//   B fragments LDG'd from g_Wf with DISTANCE-2 rolling 3-slot prefetch
//   (issue-to-use ~2 iterations, covers L2-hit latency ~240cyc).
//   A frags loaded in two mf half-rounds (halves live A regs).
//   8 warps, warp tile 64x32 (1m x 8n over CTA 64x256). vt2: 64x16.
// ---------------------------------------------------------------------------
#define JSMEM 65536                 // A only

template<int NF>
__device__ __forceinline__ void run_vt(
    uint32_t sbA, const uint2* __restrict__ wbase,
    const float* __restrict__ bout, float* __restrict__ outbt,
    int vtn0, int rowA, uint32_t swz, int khA, int l)
{
    int gr = l >> 2, ct = l & 3;
    float acc[4][NF][4];
    #pragma unroll
    for (int nf = 0; nf < NF; nf++) {
        int cc = vtn0 + nf * 8 + 2 * ct;
        float b0 = __ldg(&bout[cc]), b1 = __ldg(&bout[cc + 1]);
        #pragma unroll
        for (int mf = 0; mf < 4; mf++) {
            acc[mf][nf][0] = b0; acc[mf][nf][1] = b1;
            acc[mf][nf][2] = b0; acc[mf][nf][3] = b1;
        }
    }

    uint2 bf[3][NF];
    #pragma unroll
    for (int p = 0; p < 2; p++)
        #pragma unroll
        for (int nb = 0; nb < NF; nb++)
            bf[p][nb] = __ldg(wbase + nb * 1024 + p * 32);

    // One ks iteration; cur = ks%3 (compile-time). Prefetch for ks+2 is
    // issued FIRST (into the slot freed at ks-1) → ~2 iterations of cover.
    #define KS_ITER(ks, cur)                                                  \
    do {                                                                      \
        if ((ks) + 2 < 32) {                                                  \
            _Pragma("unroll")                                                 \
            for (int nb = 0; nb < NF; nb++)                                   \
                bf[((cur) + 2) % 3][nb] =                                     \
                    __ldg(wbase + nb * 1024 + ((ks) + 2) * 32);               \
        }                                                                     \
        uint32_t bc = (uint32_t)((ks) * 32 + khA) ^ swz;                      \
        uint32_t a[2][4];                                                     \
        _Pragma("unroll")                                                     \
        for (int mf = 0; mf < 2; mf++)                                        \
            ldmx4(a[mf], sbA + (uint32_t)(mf * 16 + rowA) * 1024 + bc);       \
        _Pragma("unroll")                                                     \
        for (int mf = 0; mf < 2; mf++)                                        \
            _Pragma("unroll")                                                 \
            for (int nf = 0; nf < NF; nf++)                                   \
                mma16816(acc[mf][nf], a[mf], bf[cur][nf].x, bf[cur][nf].y);   \
        _Pragma("unroll")                                                     \
        for (int mf = 0; mf < 2; mf++)                                        \
            ldmx4(a[mf], sbA + (uint32_t)((mf + 2) * 16 + rowA) * 1024 + bc); \
        _Pragma("unroll")                                                     \
        for (int mf = 0; mf < 2; mf++)                                        \
            _Pragma("unroll")                                                 \
            for (int nf = 0; nf < NF; nf++)                                   \
                mma16816(acc[mf + 2][nf], a[mf], bf[cur][nf].x, bf[cur][nf].y); \
    } while (0)

    for (int ks = 0; ks < 30; ks += 3) {
        KS_ITER(ks, 0);
        KS_ITER(ks + 1, 1);
        KS_ITER(ks + 2, 2);
    }
    KS_ITER(30, 0);
    KS_ITER(31, 1);
    #undef KS_ITER

    // Epilogue (bias already folded in).
    #pragma unroll
    for (int nf = 0; nf < NF; nf++) {
        int cc = vtn0 + nf * 8 + 2 * ct;
        #pragma unroll
        for (int mf = 0; mf < 4; mf++) {
            int u = mf * 16 + gr;
            float* p = outbt + (size_t)u * Vc + cc;
            float2 t0; t0.x = acc[mf][nf][0]; t0.y = acc[mf][nf][1];
            float2 t1; t1.x = acc[mf][nf][2]; t1.y = acc[mf][nf][3];
            *(float2*)p = t0;
            *(float2*)(p + 8 * Vc) = t1;
        }
    }
}

__global__ __launch_bounds__(256, 2) void joint_kernel(
    const float* __restrict__ bout, float* __restrict__ out)
{
    extern __shared__ char smem[];
    uint32_t sbA = smem_u32(smem);
    int tid = threadIdx.x, l = tid & 31, w = tid >> 5;
    int bx = blockIdx.x;
    int bt = bx >> 1, uh = bx & 1;
    int b = bt >> 8;
    const float* encR = g_enc + (size_t)bt * Hc;
    const float* decB = g_dec + ((size_t)b * Uc + uh * 64) * Hc;

    // Fill A[64][512]: rows have 1024B stride, SW128-style XOR swizzle.
    #pragma unroll
    for (int i = 0; i < 16; i++) {
        int idx = i * 256 + tid;          // 4096 units of 8 halfs
        int r = idx >> 6, cg = idx & 63;
        int kc = cg * 8;
        float4 d0 = *(const float4*)(decB + (size_t)r * Hc + kc);
        float4 d1 = *(const float4*)(decB + (size_t)r * Hc + kc + 4);
        float4 e0 = *(const float4*)(encR + kc);
        float4 e1 = *(const float4*)(encR + kc + 4);
        uint4 q;
        q.x = pack2(tanh_fast(d0.x + e0.x), tanh_fast(d0.y + e0.y));
        q.y = pack2(tanh_fast(d0.z + e0.z), tanh_fast(d0.w + e0.w));
        q.z = pack2(tanh_fast(d1.x + e1.x), tanh_fast(d1.y + e1.y));
        q.w = pack2(tanh_fast(d1.z + e1.z), tanh_fast(d1.w + e1.w));
        uint32_t off = (uint32_t)r * 1024 + (((uint32_t)cg * 16) ^ (((uint32_t)r & 7) << 4));
        asm volatile("st.shared.v4.b32 [%0], {%1,%2,%3,%4};"
                     :: "r"(sbA + off), "r"(q.x), "r"(q.y), "r"(q.z), "r"(q.w)
                     : "memory");
    }
    __syncthreads();   // the ONLY barrier

    int rowA = l & 15, khA = (l >> 4) * 16;
    uint32_t swz = ((uint32_t)l & 7) << 4;
    float* outbt = out + ((size_t)bt * Uc + uh * 64) * Vc;

    {
        int n0 = w * 32;
        const uint2* wb = g_Wf + (size_t)(n0 >> 3) * 1024 + l;
        run_vt<4>(sbA, wb, bout, outbt, n0, rowA, swz, khA, l);
    }
    {
        int n0 = 256 + w * 32;
        const uint2* wb = g_Wf + (size_t)(n0 >> 3) * 1024 + l;
        run_vt<4>(sbA, wb, bout, outbt, n0, rowA, swz, khA, l);
    }
    {
        int n0 = 512 + w * 16;
        const uint2* wb = g_Wf + (size_t)(n0 >> 3) * 1024 + l;
        run_vt<2>(sbA, wb, bout, outbt, n0, rowA, swz, khA, l);
    }
}

// ---------------------------------------------------------------------------
extern "C" void kernel_launch(void* const* d_in, const int* in_sizes, int n_in,
                              void* d_out, int out_size)
{
    const float* enc_out = (const float*)d_in[0];
    const float* dec_out = (const float*)d_in[1];
    const float* W_enc   = (const float*)d_in[2];
    const float* b_enc   = (const float*)d_in[3];
    const float* W_dec   = (const float*)d_in[4];
    const float* W_out   = (const float*)d_in[5];
    const float* b_out   = (const float*)d_in[6];
    float* out = (float*)d_out;

    cudaFuncSetAttribute(joint_kernel,
                         cudaFuncAttributeMaxDynamicSharedMemorySize, JSMEM);

    prep_kernel<<<dim3(8, 16, 3), 256>>>(enc_out, dec_out, W_enc, b_enc, W_dec, W_out);
    joint_kernel<<<2 * Bc * Tc, 256, JSMEM>>>(b_out, out);
}